// round 6
// baseline (speedup 1.0000x reference)
#include <cuda_runtime.h>
#include <cuda_bf16.h>
#include <cstdint>

#define NB 4
#define NC 256
#define NPIX 4096
#define ND 32

// ---------------- device scratch ----------------
__device__ __align__(256) __nv_bfloat16 g_q[(size_t)NB * NPIX * ND];   // [b][n][d]
__device__ __align__(256) __nv_bfloat16 g_k[(size_t)NB * NPIX * ND];   // [b][n][d]
__device__ __align__(256) __nv_bfloat16 g_v[(size_t)NB * NPIX * NC];   // [b][n][c]
__device__ __align__(256) __nv_bfloat16 g_xbf[(size_t)NB * NC * NPIX]; // [b][c][n]
__device__ __align__(256) __nv_bfloat16 g_wall[320 * NC];              // q(32),k(32),v(256) rows
__device__ __align__(256) float         g_ball[320];

// ---------------- PTX helpers ----------------
__device__ __forceinline__ uint32_t smem_u32(const void* p) {
    uint32_t a;
    asm("{ .reg .u64 t; cvta.to.shared.u64 t, %1; cvt.u32.u64 %0, t; }" : "=r"(a) : "l"(p));
    return a;
}
__device__ __forceinline__ void cp16(uint32_t dst, const void* src) {
    asm volatile("cp.async.cg.shared.global [%0], [%1], 16;" :: "r"(dst), "l"(src));
}
#define CP_COMMIT() asm volatile("cp.async.commit_group;" ::: "memory")
#define CP_WAIT1()  asm volatile("cp.async.wait_group 1;" ::: "memory")
#define CP_WAIT0()  asm volatile("cp.async.wait_group 0;" ::: "memory")

__device__ __forceinline__ void ldsm4(uint32_t r[4], uint32_t addr) {
    asm volatile("ldmatrix.sync.aligned.m8n8.x4.shared.b16 {%0,%1,%2,%3}, [%4];"
        : "=r"(r[0]), "=r"(r[1]), "=r"(r[2]), "=r"(r[3]) : "r"(addr));
}
__device__ __forceinline__ void ldsm4t(uint32_t r[4], uint32_t addr) {
    asm volatile("ldmatrix.sync.aligned.m8n8.x4.trans.shared.b16 {%0,%1,%2,%3}, [%4];"
        : "=r"(r[0]), "=r"(r[1]), "=r"(r[2]), "=r"(r[3]) : "r"(addr));
}
__device__ __forceinline__ void mma16816(float c[4], const uint32_t a[4],
                                         uint32_t b0, uint32_t b1) {
    asm volatile(
        "mma.sync.aligned.m16n8k16.row.col.f32.bf16.bf16.f32 "
        "{%0,%1,%2,%3}, {%4,%5,%6,%7}, {%8,%9}, {%0,%1,%2,%3};"
        : "+f"(c[0]), "+f"(c[1]), "+f"(c[2]), "+f"(c[3])
        : "r"(a[0]), "r"(a[1]), "r"(a[2]), "r"(a[3]), "r"(b0), "r"(b1));
}
__device__ __forceinline__ uint32_t packbf(float lo, float hi) {
    uint32_t r;
    asm("cvt.rn.satfinite.bf16x2.f32 %0, %1, %2;" : "=r"(r) : "f"(hi), "f"(lo));
    return r;
}

// ---------------- kernel 0a: x -> bf16 ----------------
__global__ void __launch_bounds__(256)
xconvert(const float* __restrict__ x, __nv_bfloat16* __restrict__ xbf)
{
    size_t i4 = (size_t)blockIdx.x * 256 + threadIdx.x;
    float4 v = reinterpret_cast<const float4*>(x)[i4];
    uint2 o;
    o.x = packbf(v.x, v.y);
    o.y = packbf(v.z, v.w);
    reinterpret_cast<uint2*>(xbf)[i4] = o;
}

// ---------------- kernel 0b: pack Wq/Wk/Wv + biases ----------------
__global__ void __launch_bounds__(256)
packw(const float* __restrict__ Wq, const float* __restrict__ bq,
      const float* __restrict__ Wk, const float* __restrict__ bk,
      const float* __restrict__ Wv, const float* __restrict__ bv,
      __nv_bfloat16* __restrict__ wall, float* __restrict__ ball)
{
    int r = blockIdx.x;
    int c = threadIdx.x;
    float wv, bvl;
    if (r < 32)       { wv = Wq[(size_t)r * NC + c];        bvl = bq[r]; }
    else if (r < 64)  { wv = Wk[(size_t)(r - 32) * NC + c]; bvl = bk[r - 32]; }
    else              { wv = Wv[(size_t)(r - 64) * NC + c]; bvl = bv[r - 64]; }
    wall[(size_t)r * NC + c] = __float2bfloat16(wv);
    if (c == 0) ball[r] = bvl;
}

// ---------------- kernel 1: fused HMMA projection (unchanged from R5) ----------------
#define XSTR 144
#define WSTR 528
#define PSM_X 0
#define PSM_W (256 * XSTR)
#define PSM_TOTAL (PSM_W + 320 * WSTR)

__global__ void __launch_bounds__(256, 1)
proj_fused(const __nv_bfloat16* __restrict__ xbf,
           const __nv_bfloat16* __restrict__ wall,
           const float* __restrict__ ball,
           __nv_bfloat16* __restrict__ q,
           __nv_bfloat16* __restrict__ k,
           __nv_bfloat16* __restrict__ v)
{
    extern __shared__ char smem[];
    const uint32_t sb = smem_u32(smem);
    const int b   = blockIdx.y;
    const int n0  = blockIdx.x * 64;
    const int tid = threadIdx.x;
    const int w = tid >> 5, lane = tid & 31;
    const int m0  = (w >> 1) * 16;
    const int ncb = (w & 1) * 160;
    const int grp = lane >> 3, rr = lane & 7;
    const int gr = lane >> 2, lc = lane & 3;

    #pragma unroll
    for (int it = 0; it < 8; ++it) {
        int idx = tid + it * 256;
        int r = idx >> 3, c = idx & 7;
        cp16(sb + PSM_X + (uint32_t)r * XSTR + c * 16,
             xbf + ((size_t)b * NC + r) * NPIX + n0 + c * 8);
    }
    #pragma unroll
    for (int it = 0; it < 40; ++it) {
        int idx = tid + it * 256;
        int r = idx >> 5, c = idx & 31;
        cp16(sb + PSM_W + (uint32_t)r * WSTR + c * 16,
             wall + (size_t)r * NC + c * 8);
    }
    CP_COMMIT();
    CP_WAIT0();
    __syncthreads();

    float acc[20][4];
    #pragma unroll
    for (int j = 0; j < 20; ++j)
        #pragma unroll
        for (int i = 0; i < 4; ++i) acc[j][i] = 0.f;

    #pragma unroll 4
    for (int ks = 0; ks < 16; ++ks) {
        uint32_t af[4];
        ldsm4t(af, sb + PSM_X
                   + (uint32_t)(ks * 16 + (grp >> 1) * 8 + rr) * XSTR
                   + (m0 + (grp & 1) * 8) * 2);
        #pragma unroll
        for (int j = 0; j < 10; ++j) {
            uint32_t bfr[4];
            ldsm4(bfr, sb + PSM_W
                       + (uint32_t)(ncb + j * 16 + (grp >> 1) * 8 + rr) * WSTR
                       + ks * 32 + (grp & 1) * 16);
            mma16816(acc[2 * j],     af, bfr[0], bfr[1]);
            mma16816(acc[2 * j + 1], af, bfr[2], bfr[3]);
        }
    }

    const int row0 = n0 + m0 + gr;
    #pragma unroll
    for (int j = 0; j < 20; ++j) {
        int col = ncb + j * 8 + 2 * lc;
        float b0 = ball[col], b1 = ball[col + 1];
        uint32_t lop = packbf(acc[j][0] + b0, acc[j][1] + b1);
        uint32_t hip = packbf(acc[j][2] + b0, acc[j][3] + b1);
        uint32_t* dst;
        int cc;
        if (col < 32)      { dst = reinterpret_cast<uint32_t*>(q); cc = col;
                             size_t r0 = ((size_t)b * NPIX + row0) * ND + cc;
                             dst[r0 >> 1] = lop;
                             dst[(r0 + 8 * ND) >> 1] = hip; }
        else if (col < 64) { dst = reinterpret_cast<uint32_t*>(k); cc = col - 32;
                             size_t r0 = ((size_t)b * NPIX + row0) * ND + cc;
                             dst[r0 >> 1] = lop;
                             dst[(r0 + 8 * ND) >> 1] = hip; }
        else               { dst = reinterpret_cast<uint32_t*>(v); cc = col - 64;
                             size_t r0 = ((size_t)b * NPIX + row0) * NC + cc;
                             dst[r0 >> 1] = lop;
                             dst[(r0 + 8 * NC) >> 1] = hip; }
    }
}

// ---------------- kernel 2: HMMA flash attention, software-pipelined ----------------
// Per tile t:  prefetch(t+1) -> QK(t) -> PV(t-1) -> exp(t).
// V triple-buffered so PV(t-1)'s buffer is not being overwritten by V(t+1).
#define KSTRIDE 80
#define VSTRIDE 528
#define SQ  0
#define SK0 (SQ  + 64 * KSTRIDE)
#define SK1 (SK0 + 64 * KSTRIDE)
#define SV0 (SK1 + 64 * KSTRIDE)
#define SV1 (SV0 + 64 * VSTRIDE)
#define SV2 (SV1 + 64 * VSTRIDE)
#define SM_TOTAL (SV2 + 64 * VSTRIDE)   // 116736 bytes

__global__ void __launch_bounds__(256, 1)
attn_kernel(const float* __restrict__ x, const float* __restrict__ gamma,
            float* __restrict__ out)
{
    extern __shared__ char smem[];
    const uint32_t sb = smem_u32(smem);
    const int b   = blockIdx.y;
    const int n0q = blockIdx.x * 64;
    const int tid = threadIdx.x;
    const int w = tid >> 5, lane = tid & 31;
    const int qb = w >> 1;
    const int ch = w & 1;
    const int grp = lane >> 3, rr = lane & 7;
    const int gr = lane >> 2, lc = lane & 3;

    const __nv_bfloat16* qg = g_q + ((size_t)b * NPIX + n0q) * ND;
    const __nv_bfloat16* kg = g_k + (size_t)b * NPIX * ND;
    const __nv_bfloat16* vg = g_v + (size_t)b * NPIX * NC;

    // ---- prologue: Q + K0 + V0 (group 0) ----
    {
        int r = tid >> 2, c = tid & 3;
        cp16(sb + SQ + (uint32_t)r * KSTRIDE + c * 16, qg + (size_t)r * ND + c * 8);
        cp16(sb + SK0 + (uint32_t)r * KSTRIDE + c * 16, kg + (size_t)r * ND + c * 8);
    }
    #pragma unroll
    for (int it = 0; it < 8; ++it) {
        int idx = tid + it * 256;
        int r = idx >> 5, c = idx & 31;
        cp16(sb + SV0 + (uint32_t)r * VSTRIDE + c * 16, vg + (size_t)r * NC + c * 8);
    }
    CP_COMMIT();

    float Oacc[16][4];
    #pragma unroll
    for (int i = 0; i < 16; ++i)
        #pragma unroll
        for (int j = 0; j < 4; ++j) Oacc[i][j] = 0.f;
    float l_lo = 0.f, l_hi = 0.f;
    uint32_t qf[2][4];
    uint32_t pf[4][4];           // P(t) fragments, consumed at t+1

    for (int t = 0; t < 64; ++t) {
        // ---- prefetch tile t+1 ----
        if (t < 63) {
            const uint32_t kbufN = sb + (((t + 1) & 1) ? SK1 : SK0);
            const uint32_t vbufN = sb + SV0 + (uint32_t)((t + 1) % 3) * (64 * VSTRIDE);
            const int k0n = (t + 1) * 64;
            {
                int r = tid >> 2, c = tid & 3;
                cp16(kbufN + (uint32_t)r * KSTRIDE + c * 16,
                     kg + (size_t)(k0n + r) * ND + c * 8);
            }
            #pragma unroll
            for (int it = 0; it < 8; ++it) {
                int idx = tid + it * 256;
                int r = idx >> 5, c = idx & 31;
                cp16(vbufN + (uint32_t)r * VSTRIDE + c * 16,
                     vg + (size_t)(k0n + r) * NC + c * 8);
            }
            CP_COMMIT();
            CP_WAIT1();          // tile t fully arrived; t+1 in flight
        } else {
            CP_WAIT0();
        }
        __syncthreads();

        if (t == 0) {
            #pragma unroll
            for (int ks = 0; ks < 2; ++ks) {
                uint32_t addr = sb + SQ
                    + (uint32_t)(qb * 16 + (grp & 1) * 8 + rr) * KSTRIDE
                    + ks * 32 + (grp >> 1) * 16;
                ldsm4(qf[ks], addr);
            }
        }

        // ---- QK(t): S = Q * K^T ----
        const uint32_t kbuf = sb + ((t & 1) ? SK1 : SK0);
        float sacc[8][4];
        #pragma unroll
        for (int i = 0; i < 8; ++i)
            #pragma unroll
            for (int j = 0; j < 4; ++j) sacc[i][j] = 0.f;
        #pragma unroll
        for (int ks = 0; ks < 2; ++ks) {
            #pragma unroll
            for (int p = 0; p < 4; ++p) {
                uint32_t bfr[4];
                uint32_t addr = kbuf
                    + (uint32_t)(p * 16 + (grp >> 1) * 8 + rr) * KSTRIDE
                    + ks * 32 + (grp & 1) * 16;
                ldsm4(bfr, addr);
                mma16816(sacc[2 * p],     qf[ks], bfr[0], bfr[1]);
                mma16816(sacc[2 * p + 1], qf[ks], bfr[2], bfr[3]);
            }
        }

        // ---- PV(t-1): O += P(t-1) * V(t-1)  (tensor pipe stays busy while
        //      exp below waits on sacc) ----
        if (t > 0) {
            const uint32_t vbufP = sb + SV0 + (uint32_t)((t + 2) % 3) * (64 * VSTRIDE);
            #pragma unroll
            for (int kb = 0; kb < 4; ++kb) {
                #pragma unroll
                for (int np = 0; np < 8; ++np) {
                    uint32_t bfr[4];
                    uint32_t addr = vbufP
                        + (uint32_t)(kb * 16 + (grp & 1) * 8 + rr) * VSTRIDE
                        + ch * 256 + np * 32 + (grp >> 1) * 16;
                    ldsm4t(bfr, addr);
                    mma16816(Oacc[2 * np],     pf[kb], bfr[0], bfr[1]);
                    mma16816(Oacc[2 * np + 1], pf[kb], bfr[2], bfr[3]);
                }
            }
        }

        // ---- exp(t) -> pf ----
        #pragma unroll
        for (int nt = 0; nt < 8; ++nt) {
            float e0 = __expf(sacc[nt][0]);
            float e1 = __expf(sacc[nt][1]);
            float e2 = __expf(sacc[nt][2]);
            float e3 = __expf(sacc[nt][3]);
            l_lo += e0 + e1;
            l_hi += e2 + e3;
            int kb = nt >> 1;
            if ((nt & 1) == 0) {
                pf[kb][0] = packbf(e0, e1);
                pf[kb][1] = packbf(e2, e3);
            } else {
                pf[kb][2] = packbf(e0, e1);
                pf[kb][3] = packbf(e2, e3);
            }
        }

        __syncthreads();   // all reads of V(t-1)/K(t) done before next prefetch overwrites
    }

    // ---- drain: PV(63) ----
    {
        const uint32_t vbufP = sb + SV0 + (uint32_t)(63 % 3) * (64 * VSTRIDE);
        #pragma unroll
        for (int kb = 0; kb < 4; ++kb) {
            #pragma unroll
            for (int np = 0; np < 8; ++np) {
                uint32_t bfr[4];
                uint32_t addr = vbufP
                    + (uint32_t)(kb * 16 + (grp & 1) * 8 + rr) * VSTRIDE
                    + ch * 256 + np * 32 + (grp >> 1) * 16;
                ldsm4t(bfr, addr);
                mma16816(Oacc[2 * np],     pf[kb], bfr[0], bfr[1]);
                mma16816(Oacc[2 * np + 1], pf[kb], bfr[2], bfr[3]);
            }
        }
    }

    l_lo += __shfl_xor_sync(0xFFFFFFFF, l_lo, 1);
    l_lo += __shfl_xor_sync(0xFFFFFFFF, l_lo, 2);
    l_hi += __shfl_xor_sync(0xFFFFFFFF, l_hi, 1);
    l_hi += __shfl_xor_sync(0xFFFFFFFF, l_hi, 2);
    const float gma = gamma[0];
    const float inv_lo = gma / l_lo;
    const float inv_hi = gma / l_hi;

    const int pix0 = n0q + qb * 16 + gr;
    #pragma unroll
    for (int nt = 0; nt < 16; ++nt) {
        int c0 = ch * 128 + nt * 8 + 2 * lc;
        size_t i00 = ((size_t)b * NC + c0) * NPIX + pix0;
        size_t i01 = i00 + NPIX;
        out[i00] = Oacc[nt][0] * inv_lo + x[i00];
        out[i01] = Oacc[nt][1] * inv_lo + x[i01];
        size_t i10 = i00 + 8;
        size_t i11 = i01 + 8;
        out[i10] = Oacc[nt][2] * inv_hi + x[i10];
        out[i11] = Oacc[nt][3] * inv_hi + x[i11];
    }
}

// ---------------- launch ----------------
extern "C" void kernel_launch(void* const* d_in, const int* in_sizes, int n_in,
                              void* d_out, int out_size)
{
    (void)in_sizes; (void)n_in; (void)out_size;
    const float* x     = (const float*)d_in[0];
    const float* Wq    = (const float*)d_in[1];
    const float* bq    = (const float*)d_in[2];
    const float* Wk    = (const float*)d_in[3];
    const float* bk    = (const float*)d_in[4];
    const float* Wv    = (const float*)d_in[5];
    const float* bv    = (const float*)d_in[6];
    const float* gamma = (const float*)d_in[7];
    float* out = (float*)d_out;

    void* p;
    cudaGetSymbolAddress(&p, g_q);    __nv_bfloat16* qT  = (__nv_bfloat16*)p;
    cudaGetSymbolAddress(&p, g_k);    __nv_bfloat16* kT  = (__nv_bfloat16*)p;
    cudaGetSymbolAddress(&p, g_v);    __nv_bfloat16* vT  = (__nv_bfloat16*)p;
    cudaGetSymbolAddress(&p, g_xbf);  __nv_bfloat16* xbf = (__nv_bfloat16*)p;
    cudaGetSymbolAddress(&p, g_wall); __nv_bfloat16* wal = (__nv_bfloat16*)p;
    cudaGetSymbolAddress(&p, g_ball); float*         bal = (float*)p;

    static int attr_set = 0;
    if (!attr_set) {
        cudaFuncSetAttribute(attn_kernel,
                             cudaFuncAttributeMaxDynamicSharedMemorySize, SM_TOTAL);
        cudaFuncSetAttribute(proj_fused,
                             cudaFuncAttributeMaxDynamicSharedMemorySize, PSM_TOTAL);
        attr_set = 1;
    }

    xconvert<<<(NB * NC * NPIX) / (256 * 4), 256>>>(x, xbf);
    packw<<<320, 256>>>(Wq, bq, Wk, bk, Wv, bv, wal, bal);
    proj_fused<<<dim3(NPIX / 64, NB), 256, PSM_TOTAL>>>(xbf, wal, bal, qT, kT, vT);
    attn_kernel<<<dim3(NPIX / 64, NB), 256, SM_TOTAL>>>(x, gamma, out);
}